// round 1
// baseline (speedup 1.0000x reference)
#include <cuda_runtime.h>
#include <cuda_bf16.h>

// MedianFilter1D: x[16, 64, 16384] fp32, window k=9, zero padding.
// 1024 rows x 16384. Each thread produces 8 consecutive outputs.
//
// Trick: windows o and o+1 share 8 elements. Sort the shared 8 (Batcher
// 19-comparator network; compiler DCEs everything outside the s3/s4 cone),
// then median-of-9 with one inserted element x is exactly
//   clamp(x, s3, s4) = min(max(x, s3), s4)
// (5th order stat of 9 = x clamped between 4th and 5th order stats of the 8).

#define CE(a, b) { float _lo = fminf(a, b); float _hi = fmaxf(a, b); (a) = _lo; (b) = _hi; }

__device__ __forceinline__ void rank34_of8(
    float a0, float a1, float a2, float a3,
    float a4, float a5, float a6, float a7,
    float& s3, float& s4)
{
    // Batcher odd-even merge sort for 8 (19 compare-exchanges).
    CE(a0, a1) CE(a2, a3) CE(a4, a5) CE(a6, a7)
    CE(a0, a2) CE(a1, a3) CE(a4, a6) CE(a5, a7)
    CE(a1, a2) CE(a5, a6)
    CE(a0, a4) CE(a1, a5) CE(a2, a6) CE(a3, a7)
    CE(a2, a4) CE(a3, a5)
    CE(a1, a2) CE(a3, a4) CE(a5, a6)
    s3 = a3;  // 4th smallest (0-indexed rank 3)
    s4 = a4;  // 5th smallest (rank 4)
}

static constexpr int L       = 16384;
static constexpr int ROWS    = 16 * 64;     // 1024
static constexpr int OPT     = 8;           // outputs per thread
static constexpr int TPB     = 256;
static constexpr int THREADS_PER_ROW = L / OPT;  // 2048

__global__ __launch_bounds__(TPB)
void median9_kernel(const float* __restrict__ x, float* __restrict__ y)
{
    int t   = blockIdx.x * TPB + threadIdx.x;     // global thread id
    int row = t >> 11;                            // t / 2048
    int cb  = (t & (THREADS_PER_ROW - 1)) << 3;   // column base, multiple of 8

    const float* rp = x + (size_t)row * L;

    // Inputs v[i] = x[row, cb - 4 + i], i in [0, 16)
    float v[16];
    if (cb >= 4 && cb + 12 <= L) {
        // cb - 4 is a multiple of 4 -> aligned float4 loads
        const float4* p = reinterpret_cast<const float4*>(rp + cb - 4);
        float4 a0 = p[0], a1 = p[1], a2 = p[2], a3 = p[3];
        v[0] = a0.x;  v[1] = a0.y;  v[2]  = a0.z;  v[3]  = a0.w;
        v[4] = a1.x;  v[5] = a1.y;  v[6]  = a1.z;  v[7]  = a1.w;
        v[8] = a2.x;  v[9] = a2.y;  v[10] = a2.z;  v[11] = a2.w;
        v[12] = a3.x; v[13] = a3.y; v[14] = a3.z;  v[15] = a3.w;
    } else {
        #pragma unroll
        for (int i = 0; i < 16; i++) {
            int c = cb - 4 + i;
            v[i] = (c >= 0 && c < L) ? rp[c] : 0.0f;
        }
    }

    float o[8];
    #pragma unroll
    for (int j = 0; j < 4; j++) {
        int b = 2 * j;
        // Shared 8 elements between windows b and b+1: v[b+1 .. b+8]
        float s3, s4;
        rank34_of8(v[b + 1], v[b + 2], v[b + 3], v[b + 4],
                   v[b + 5], v[b + 6], v[b + 7], v[b + 8], s3, s4);
        o[b]     = fminf(fmaxf(v[b],     s3), s4);  // window b inserts v[b]
        o[b + 1] = fminf(fmaxf(v[b + 9], s3), s4);  // window b+1 inserts v[b+9]
    }

    float4* op = reinterpret_cast<float4*>(y + (size_t)row * L + cb);
    op[0] = make_float4(o[0], o[1], o[2], o[3]);
    op[1] = make_float4(o[4], o[5], o[6], o[7]);
}

extern "C" void kernel_launch(void* const* d_in, const int* in_sizes, int n_in,
                              void* d_out, int out_size)
{
    const float* x = (const float*)d_in[0];
    float* y = (float*)d_out;

    int total_threads = ROWS * THREADS_PER_ROW;   // 2,097,152
    int blocks = total_threads / TPB;             // 8192
    median9_kernel<<<blocks, TPB>>>(x, y);
}

// round 2
// speedup vs baseline: 1.0102x; 1.0102x over previous
#include <cuda_runtime.h>
#include <cuda_bf16.h>

// MedianFilter1D: x[16, 64, 16384] fp32, window k=9, zero padding.
// 1024 rows x 16384. Each thread produces 8 consecutive outputs.
//
// Round 2: each thread loads ONLY its own 8 floats (2 aligned LDG.128 —
// zero read redundancy); the 4-float left/right halos come from adjacent
// lanes via __shfl_sync. Only lane 0 / lane 31 of each warp do one extra
// guarded float4 load (cross-warp halo). This halves L1 traffic vs R1.
//
// Median trick (unchanged): windows o and o+1 share 8 elements. Sort the
// shared 8 (Batcher; DCE prunes to the rank-3/4 cone), then
//   median9 = min(max(x_inserted, s3), s4).

#define CE(a, b) { float _lo = fminf(a, b); float _hi = fmaxf(a, b); (a) = _lo; (b) = _hi; }

__device__ __forceinline__ void rank34_of8(
    float a0, float a1, float a2, float a3,
    float a4, float a5, float a6, float a7,
    float& s3, float& s4)
{
    CE(a0, a1) CE(a2, a3) CE(a4, a5) CE(a6, a7)
    CE(a0, a2) CE(a1, a3) CE(a4, a6) CE(a5, a7)
    CE(a1, a2) CE(a5, a6)
    CE(a0, a4) CE(a1, a5) CE(a2, a6) CE(a3, a7)
    CE(a2, a4) CE(a3, a5)
    CE(a1, a2) CE(a3, a4) CE(a5, a6)
    s3 = a3;
    s4 = a4;
}

static constexpr int L    = 16384;
static constexpr int ROWS = 16 * 64;           // 1024
static constexpr int TPB  = 256;
static constexpr int THREADS_PER_ROW = L / 8;  // 2048 (warp = 256 contiguous cols)

__global__ __launch_bounds__(TPB)
void median9_kernel(const float* __restrict__ x, float* __restrict__ y)
{
    const unsigned FULL = 0xFFFFFFFFu;
    int t    = blockIdx.x * TPB + threadIdx.x;
    int lane = threadIdx.x & 31;
    int row  = t >> 11;                          // t / 2048
    int cb   = (t & (THREADS_PER_ROW - 1)) << 3; // column base, multiple of 8

    const float* rp = x + (size_t)row * L;

    // Own 8 floats: cols [cb, cb+8) — always fully in range, 16B-aligned.
    float4 lo = *reinterpret_cast<const float4*>(rp + cb);
    float4 hi = *reinterpret_cast<const float4*>(rp + cb + 4);

    // Left halo v[0..4) = cols [cb-4, cb) = previous thread's `hi`.
    float4 lh;
    lh.x = __shfl_up_sync(FULL, hi.x, 1);
    lh.y = __shfl_up_sync(FULL, hi.y, 1);
    lh.z = __shfl_up_sync(FULL, hi.z, 1);
    lh.w = __shfl_up_sync(FULL, hi.w, 1);
    // Right halo v[12..16) = cols [cb+8, cb+12) = next thread's `lo`.
    float4 rh;
    rh.x = __shfl_down_sync(FULL, lo.x, 1);
    rh.y = __shfl_down_sync(FULL, lo.y, 1);
    rh.z = __shfl_down_sync(FULL, lo.z, 1);
    rh.w = __shfl_down_sync(FULL, lo.w, 1);

    // Warp-edge fixups (cross-warp halo, or zero padding at row ends).
    if (lane == 0) {
        if (cb > 0) lh = *reinterpret_cast<const float4*>(rp + cb - 4);
        else        lh = make_float4(0.f, 0.f, 0.f, 0.f);
    }
    if (lane == 31) {
        if (cb + 12 <= L) rh = *reinterpret_cast<const float4*>(rp + cb + 8);
        else              rh = make_float4(0.f, 0.f, 0.f, 0.f);
    }

    float v[16];
    v[0]  = lh.x; v[1]  = lh.y; v[2]  = lh.z; v[3]  = lh.w;
    v[4]  = lo.x; v[5]  = lo.y; v[6]  = lo.z; v[7]  = lo.w;
    v[8]  = hi.x; v[9]  = hi.y; v[10] = hi.z; v[11] = hi.w;
    v[12] = rh.x; v[13] = rh.y; v[14] = rh.z; v[15] = rh.w;

    float o[8];
    #pragma unroll
    for (int j = 0; j < 4; j++) {
        int b = 2 * j;
        float s3, s4;
        rank34_of8(v[b + 1], v[b + 2], v[b + 3], v[b + 4],
                   v[b + 5], v[b + 6], v[b + 7], v[b + 8], s3, s4);
        o[b]     = fminf(fmaxf(v[b],     s3), s4);
        o[b + 1] = fminf(fmaxf(v[b + 9], s3), s4);
    }

    float4* op = reinterpret_cast<float4*>(y + (size_t)row * L + cb);
    op[0] = make_float4(o[0], o[1], o[2], o[3]);
    op[1] = make_float4(o[4], o[5], o[6], o[7]);
}

extern "C" void kernel_launch(void* const* d_in, const int* in_sizes, int n_in,
                              void* d_out, int out_size)
{
    const float* x = (const float*)d_in[0];
    float* y = (float*)d_out;

    int total_threads = ROWS * THREADS_PER_ROW;   // 2,097,152
    int blocks = total_threads / TPB;             // 8192
    median9_kernel<<<blocks, TPB>>>(x, y);
}

// round 3
// speedup vs baseline: 1.0435x; 1.0330x over previous
#include <cuda_runtime.h>
#include <cuda_bf16.h>

// MedianFilter1D: x[16, 64, 16384] fp32, window k=9, zero padding.
// 1024 rows x 16384. Each thread produces 8 consecutive outputs.
//
// Round 3: R2 + streaming cache hints. Input is read-once and output is
// write-once; without hints, 67 MB of output sits dirty in L2 and drains
// AFTER the kernel, serializing against the next graph replay (harness 25 µs
// vs kernel 21 µs). __ldcs/__stcs (evict-first) push writes to HBM during
// the kernel, overlapped with reads.
//
// Median trick (unchanged): windows o and o+1 share 8 elements. Sort the
// shared 8 (Batcher; DCE prunes to the rank-3/4 cone), then
//   median9 = min(max(x_inserted, s3), s4).

#define CE(a, b) { float _lo = fminf(a, b); float _hi = fmaxf(a, b); (a) = _lo; (b) = _hi; }

__device__ __forceinline__ void rank34_of8(
    float a0, float a1, float a2, float a3,
    float a4, float a5, float a6, float a7,
    float& s3, float& s4)
{
    CE(a0, a1) CE(a2, a3) CE(a4, a5) CE(a6, a7)
    CE(a0, a2) CE(a1, a3) CE(a4, a6) CE(a5, a7)
    CE(a1, a2) CE(a5, a6)
    CE(a0, a4) CE(a1, a5) CE(a2, a6) CE(a3, a7)
    CE(a2, a4) CE(a3, a5)
    CE(a1, a2) CE(a3, a4) CE(a5, a6)
    s3 = a3;
    s4 = a4;
}

static constexpr int L    = 16384;
static constexpr int ROWS = 16 * 64;           // 1024
static constexpr int TPB  = 256;
static constexpr int THREADS_PER_ROW = L / 8;  // 2048

__global__ __launch_bounds__(TPB)
void median9_kernel(const float* __restrict__ x, float* __restrict__ y)
{
    const unsigned FULL = 0xFFFFFFFFu;
    int t    = blockIdx.x * TPB + threadIdx.x;
    int lane = threadIdx.x & 31;
    int row  = t >> 11;                          // t / 2048
    int cb   = (t & (THREADS_PER_ROW - 1)) << 3; // column base, multiple of 8

    const float* rp = x + (size_t)row * L;

    // Own 8 floats: cols [cb, cb+8) — 16B-aligned, streaming (read-once).
    float4 lo = __ldcs(reinterpret_cast<const float4*>(rp + cb));
    float4 hi = __ldcs(reinterpret_cast<const float4*>(rp + cb + 4));

    // Left halo = previous lane's `hi`; right halo = next lane's `lo`.
    float4 lh;
    lh.x = __shfl_up_sync(FULL, hi.x, 1);
    lh.y = __shfl_up_sync(FULL, hi.y, 1);
    lh.z = __shfl_up_sync(FULL, hi.z, 1);
    lh.w = __shfl_up_sync(FULL, hi.w, 1);
    float4 rh;
    rh.x = __shfl_down_sync(FULL, lo.x, 1);
    rh.y = __shfl_down_sync(FULL, lo.y, 1);
    rh.z = __shfl_down_sync(FULL, lo.z, 1);
    rh.w = __shfl_down_sync(FULL, lo.w, 1);

    // Warp-edge fixups (cross-warp halo, or zero padding at row ends).
    if (lane == 0) {
        if (cb > 0) lh = __ldca(reinterpret_cast<const float4*>(rp + cb - 4));
        else        lh = make_float4(0.f, 0.f, 0.f, 0.f);
    }
    if (lane == 31) {
        if (cb + 12 <= L) rh = __ldca(reinterpret_cast<const float4*>(rp + cb + 8));
        else              rh = make_float4(0.f, 0.f, 0.f, 0.f);
    }

    float v[16];
    v[0]  = lh.x; v[1]  = lh.y; v[2]  = lh.z; v[3]  = lh.w;
    v[4]  = lo.x; v[5]  = lo.y; v[6]  = lo.z; v[7]  = lo.w;
    v[8]  = hi.x; v[9]  = hi.y; v[10] = hi.z; v[11] = hi.w;
    v[12] = rh.x; v[13] = rh.y; v[14] = rh.z; v[15] = rh.w;

    float o[8];
    #pragma unroll
    for (int j = 0; j < 4; j++) {
        int b = 2 * j;
        float s3, s4;
        rank34_of8(v[b + 1], v[b + 2], v[b + 3], v[b + 4],
                   v[b + 5], v[b + 6], v[b + 7], v[b + 8], s3, s4);
        o[b]     = fminf(fmaxf(v[b],     s3), s4);
        o[b + 1] = fminf(fmaxf(v[b + 9], s3), s4);
    }

    // Streaming stores: don't pollute L2 with 67 MB of write-once output.
    float4* op = reinterpret_cast<float4*>(y + (size_t)row * L + cb);
    __stcs(op,     make_float4(o[0], o[1], o[2], o[3]));
    __stcs(op + 1, make_float4(o[4], o[5], o[6], o[7]));
}

extern "C" void kernel_launch(void* const* d_in, const int* in_sizes, int n_in,
                              void* d_out, int out_size)
{
    const float* x = (const float*)d_in[0];
    float* y = (float*)d_out;

    int total_threads = ROWS * THREADS_PER_ROW;   // 2,097,152
    int blocks = total_threads / TPB;             // 8192
    median9_kernel<<<blocks, TPB>>>(x, y);
}